// round 8
// baseline (speedup 1.0000x reference)
#include <cuda_runtime.h>
#include <math.h>

#define LATENT 2048
#define OBS    1024
#define CTRL   512
#define SEQ    4096
#define NCTA   128
#define RPC    16        // latent rows per CTA  (NCTA*RPC == LATENT)
#define NTHR   512       // 16 warps: 4 row-groups x 4 col-chunks
#define NREP   8         // fz replication factor
#define NEP    16        // broadcast epoch words (each on own 128B line)

// ---------------- persistent device scratch (no allocations allowed) ----------------
__device__ __align__(16) float g_M  [(size_t)LATENT*LATENT]; // Wout^T Wout
__device__ __align__(16) float g_Gt [(size_t)SEQ*LATENT];    // (Wout^T x_t)   [t][l]
__device__ __align__(16) float g_Ut [(size_t)SEQ*LATENT];    // (Win tanh(u_t))[t][l]
__device__ __align__(16) float g_zpt[(size_t)SEQ*LATENT];    // z_projs (drive)[t][l]
__device__ __align__(16) float g_fz [2][NREP][LATENT];       // double-buffered, replicated tanh(z)
__device__ unsigned g_bar;                                   // arrival counter (adds only, no polls)
__device__ __align__(128) unsigned g_ep[NEP * 32];           // sharded epoch broadcast words

// ---------------- sync primitives ----------------
__device__ __forceinline__ unsigned atom_add_acqrel(unsigned* p, unsigned v) {
  unsigned old;
  asm volatile("atom.add.acq_rel.gpu.global.u32 %0, [%1], %2;"
               : "=r"(old) : "l"(p), "r"(v) : "memory");
  return old;
}
__device__ __forceinline__ void st_rel(unsigned* p, unsigned v) {
  asm volatile("st.release.gpu.global.u32 [%0], %1;" :: "l"(p), "r"(v) : "memory");
}
__device__ __forceinline__ unsigned ld_acq(const unsigned* p) {
  unsigned v;
  asm volatile("ld.acquire.gpu.global.u32 %0, [%1];" : "=r"(v) : "l"(p) : "memory");
  return v;
}

// ---------------- generic tiled fp32 GEMM ----------------
// C[Md x Nd] row-major, C[m][n] = sum_k a(k,m)*b(k,n)
//   a(k,m) = TA ? A[m*Kd + k] : A[k*Md + m]    (optionally tanh)
//   b(k,n) = TB ? B[n*Kd + k] : B[k*Nd + n]    (optionally tanh)
// RESET: block (0,0) zeroes counter, ALL broadcast words and fz copies (graph-replay safety).
template<bool TA, bool TB, bool TANHA, bool TANHB, bool RESET>
__global__ void gemm_kernel(const float* __restrict__ A, const float* __restrict__ B,
                            float* __restrict__ C, int Md, int Nd, int Kd)
{
  if (RESET && blockIdx.x == 0 && blockIdx.y == 0) {
    if (threadIdx.x == 0) g_bar = 0u;
    for (int i = threadIdx.x; i < NEP * 32; i += blockDim.x)   // FIX: cover all shards
      g_ep[i] = 0u;
    for (int i = threadIdx.x; i < 2 * NREP * LATENT; i += blockDim.x)
      ((float*)g_fz)[i] = 0.f;
  }

  __shared__ float As[16][68];
  __shared__ float Bs[16][68];
  const int tx = threadIdx.x & 15;
  const int ty = threadIdx.x >> 4;
  const int m0 = blockIdx.y * 64;
  const int n0 = blockIdx.x * 64;
  float acc[4][4];
  #pragma unroll
  for (int i = 0; i < 4; i++)
    #pragma unroll
    for (int j = 0; j < 4; j++) acc[i][j] = 0.f;

  for (int k0 = 0; k0 < Kd; k0 += 16) {
    #pragma unroll
    for (int l = 0; l < 4; l++) {
      int i = threadIdx.x + l * 256;
      int kk, mm;
      if (TA) { kk = i & 15; mm = i >> 4; } else { kk = i >> 6; mm = i & 63; }
      float v = TA ? A[(size_t)(m0 + mm) * Kd + (k0 + kk)]
                   : A[(size_t)(k0 + kk) * Md + (m0 + mm)];
      if (TANHA) v = tanhf(v);
      As[kk][mm] = v;
      int kk2, nn;
      if (TB) { kk2 = i & 15; nn = i >> 4; } else { kk2 = i >> 6; nn = i & 63; }
      float w = TB ? B[(size_t)(n0 + nn) * Kd + (k0 + kk2)]
                   : B[(size_t)(k0 + kk2) * Nd + (n0 + nn)];
      if (TANHB) w = tanhf(w);
      Bs[kk2][nn] = w;
    }
    __syncthreads();
    #pragma unroll
    for (int kk = 0; kk < 16; kk++) {
      float a[4], bb[4];
      #pragma unroll
      for (int i = 0; i < 4; i++) a[i]  = As[kk][ty * 4 + i];
      #pragma unroll
      for (int j = 0; j < 4; j++) bb[j] = Bs[kk][tx * 4 + j];
      #pragma unroll
      for (int i = 0; i < 4; i++)
        #pragma unroll
        for (int j = 0; j < 4; j++)
          acc[i][j] += a[i] * bb[j];
    }
    __syncthreads();
  }
  #pragma unroll
  for (int i = 0; i < 4; i++)
    #pragma unroll
    for (int j = 0; j < 4; j++)
      C[(size_t)(m0 + ty * 4 + i) * Nd + (n0 + tx * 4 + j)] = acc[i][j];
}

// ---------------- persistent sequential kernel ----------------
__device__ __forceinline__ void bfly4(float& a0, float& a1, float& a2, float& a3) {
  #pragma unroll
  for (int s = 16; s; s >>= 1) {
    a0 += __shfl_xor_sync(0xffffffffu, a0, s);
    a1 += __shfl_xor_sync(0xffffffffu, a1, s);
    a2 += __shfl_xor_sync(0xffffffffu, a2, s);
    a3 += __shfl_xor_sync(0xffffffffu, a3, s);
  }
}
__device__ __forceinline__ float dot4(float4 a, float4 b) {
  return a.x * b.x + a.y * b.y + a.z * b.z + a.w * b.w;
}

__global__ void __launch_bounds__(NTHR, 1)
seq_kernel(const float* __restrict__ Wr,
           const int* __restrict__ p_it, const float* __restrict__ p_lr,
           float* __restrict__ zs_out)
{
  __shared__ __align__(16) float part_m[64];   // [row*4 + chunk]
  __shared__ __align__(16) float part_w[64];   // Wr partials (k==0 only)

  const int b    = blockIdx.x;
  const int tid  = threadIdx.x;
  const int w    = tid >> 5, lane = tid & 31;
  const int g    = w >> 2;              // row group: rows 4g..4g+3
  const int c    = w & 3;               // col chunk: [512c, 512c+512)
  const int rowb = b * RPC;
  const int colb = c * 512 + lane * 16; // this lane's 16 columns
  unsigned* my_ep = &g_ep[(b & (NEP - 1)) * 32];

  // ---- M block -> registers (held live for the whole kernel) ----
  float4 Mreg[4][4];
  #pragma unroll
  for (int r = 0; r < 4; r++)
    #pragma unroll
    for (int j = 0; j < 4; j++)
      Mreg[r][j] = __ldg((const float4*)(g_M + (size_t)(rowb + 4 * g + r) * LATENT + colb) + j);

  int n_it = p_it[0];
  if (n_it <= 0 || n_it > 1000000) n_it = (int)(((const long long*)p_it)[0]);
  float lr = p_lr[0];
  if (!(lr > 1e-8f && lr < 16.f)) lr = (float)(((const double*)p_lr)[0]);

  const float4* Wr4 = (const float4*)(Wr + (size_t)(rowb + 4 * g) * LATENT + colb); // +512/row

  // per-row update state in registers of warp 0 lanes 0..15
  float z_own = 0.f, f_own = 0.f, drv = 0.f, g_r = 0.f, u_r = 0.f;

  unsigned ec = 0;                       // completed epochs; g_fz[ec&1] = current fz

  for (int t = 0; t < SEQ; t++) {
    if (tid < RPC) {
      g_r = __ldg(&g_Gt[(size_t)t * LATENT + rowb + tid]);
      u_r = __ldg(&g_Ut[(size_t)t * LATENT + rowb + tid]);
    }

    for (int k = 0; k < n_it; k++) {
      const int par = (int)(ec & 1);
      // ---- fz from this CTA's replica (L2), 4 loads in flight ----
      const float4* f4 = (const float4*)(g_fz[par][b & (NREP - 1)] + colb);
      float4 f0 = __ldcg(f4 + 0), f1 = __ldcg(f4 + 1), f2 = __ldcg(f4 + 2), f3 = __ldcg(f4 + 3);

      float a0 = dot4(Mreg[0][0], f0) + dot4(Mreg[0][1], f1) + dot4(Mreg[0][2], f2) + dot4(Mreg[0][3], f3);
      float a1 = dot4(Mreg[1][0], f0) + dot4(Mreg[1][1], f1) + dot4(Mreg[1][2], f2) + dot4(Mreg[1][3], f3);
      float a2 = dot4(Mreg[2][0], f0) + dot4(Mreg[2][1], f1) + dot4(Mreg[2][2], f2) + dot4(Mreg[2][3], f3);
      float a3 = dot4(Mreg[3][0], f0) + dot4(Mreg[3][1], f1) + dot4(Mreg[3][2], f2) + dot4(Mreg[3][3], f3);

      if (k == 0) {                      // fused drive pass: Wr rows (L1-resident across t)
        float w0 = dot4(__ldg(Wr4 + 0), f0) + dot4(__ldg(Wr4 + 1), f1)
                 + dot4(__ldg(Wr4 + 2), f2) + dot4(__ldg(Wr4 + 3), f3);
        float w1 = dot4(__ldg(Wr4 + 512), f0) + dot4(__ldg(Wr4 + 513), f1)
                 + dot4(__ldg(Wr4 + 514), f2) + dot4(__ldg(Wr4 + 515), f3);
        float w2 = dot4(__ldg(Wr4 + 1024), f0) + dot4(__ldg(Wr4 + 1025), f1)
                 + dot4(__ldg(Wr4 + 1026), f2) + dot4(__ldg(Wr4 + 1027), f3);
        float w3 = dot4(__ldg(Wr4 + 1536), f0) + dot4(__ldg(Wr4 + 1537), f1)
                 + dot4(__ldg(Wr4 + 1538), f2) + dot4(__ldg(Wr4 + 1539), f3);
        bfly4(w0, w1, w2, w3);
        if (lane < 4) {
          float v = (lane == 0) ? w0 : (lane == 1) ? w1 : (lane == 2) ? w2 : w3;
          part_w[(4 * g + lane) * 4 + c] = v;
        }
      }

      bfly4(a0, a1, a2, a3);
      if (lane < 4) {
        float v = (lane == 0) ? a0 : (lane == 1) ? a1 : (lane == 2) ? a2 : a3;
        part_m[(4 * g + lane) * 4 + c] = v;
      }
      __syncthreads();                   // partials ready

      // ---- z update + sharded broadcast barrier ----
      const unsigned en = ec + 1;
      if (tid < RPC) {
        float4 pm = *(const float4*)&part_m[tid * 4];
        float s_m = (pm.x + pm.y) + (pm.z + pm.w);
        if (k == 0) {
          float4 pw = *(const float4*)&part_w[tid * 4];
          drv = (pw.x + pw.y) + (pw.z + pw.w) + u_r;
        }
        float dz = (z_own - drv) - (1.f - f_own * f_own) * (g_r - s_m);
        z_own -= lr * dz;
        f_own = tanhf(z_own);
        #pragma unroll
        for (int cp = 0; cp < NREP; cp++)
          g_fz[par ^ 1][cp][rowb + tid] = f_own;   // 8 x 64B coalesced publishes
        __syncwarp(0x0000ffffu);
        if (tid == 0) {
          // arrive (release: fz stores ordered before); old value identifies the last CTA
          unsigned old = atom_add_acqrel(&g_bar, 1u);
          if (old == en * (unsigned)NCTA - 1u) {
            // last arriver: broadcast epoch to all shards (pollers acquire it)
            #pragma unroll
            for (int e = 0; e < NEP; e++) st_rel(&g_ep[e * 32], en);
          } else if (!(t == SEQ - 1 && k == n_it - 1)) {
            while (ld_acq(my_ep) < en) { }         // single poller, 8 CTAs/line
          }
        }
      }
      ec = en;
      __syncthreads();                   // broadcast result to all warps
    }

    // outputs: zs[:,t] (row-major LATENT x SEQ) and z_projs (drive) as [t][l]
    if (tid < RPC) {
      zs_out[(size_t)(rowb + tid) * SEQ + t] = z_own;
      g_zpt[(size_t)t * LATENT + rowb + tid] = drv;
    }
  }
}

// ---------------- launch ----------------
extern "C" void kernel_launch(void* const* d_in, const int* in_sizes, int n_in,
                              void* d_out, int out_size)
{
  const float* inputs   = (const float*)d_in[0];  // (OBS,  SEQ)
  const float* controls = (const float*)d_in[1];  // (CTRL, SEQ)
  const float* Wr       = (const float*)d_in[2];  // (LATENT, LATENT)
  const float* Win      = (const float*)d_in[3];  // (LATENT, CTRL)
  const float* Wout     = (const float*)d_in[4];  // (OBS, LATENT)
  const int*   p_it     = (const int*)d_in[5];
  const float* p_lr     = (const float*)d_in[6];

  float* zs   = (float*)d_out;                       // (LATENT, SEQ)
  float* pred = zs + (size_t)LATENT * SEQ;           // (OBS, SEQ)

  float *pM, *pGt, *pUt, *pZpt;
  cudaGetSymbolAddress((void**)&pM,   g_M);
  cudaGetSymbolAddress((void**)&pGt,  g_Gt);
  cudaGetSymbolAddress((void**)&pUt,  g_Ut);
  cudaGetSymbolAddress((void**)&pZpt, g_zpt);

  dim3 thr(256);
  // M = Wout^T Wout (+ barrier/epoch/fz reset in block 0)
  gemm_kernel<false,false,false,false,true><<<dim3(LATENT/64, LATENT/64), thr>>>(Wout, Wout, pM, LATENT, LATENT, OBS);
  // Gt[t][l] = sum_i inputs[i][t] * Wout[i][l]
  gemm_kernel<false,false,false,false,false><<<dim3(LATENT/64, SEQ/64), thr>>>(inputs, Wout, pGt, SEQ, LATENT, OBS);
  // Ut[t][l] = sum_c tanh(controls[c][t]) * Win[l][c]
  gemm_kernel<false,true,true,false,false><<<dim3(LATENT/64, SEQ/64), thr>>>(controls, Win, pUt, SEQ, LATENT, CTRL);

  seq_kernel<<<NCTA, NTHR>>>(Wr, p_it, p_lr, zs);

  // pred[i][t] = sum_l Wout[i][l] * tanh(zpt[t][l])
  gemm_kernel<true,true,false,true,false><<<dim3(SEQ/64, OBS/64), thr>>>(Wout, pZpt, pred, OBS, SEQ, LATENT);
}

// round 9
// speedup vs baseline: 3.6902x; 3.6902x over previous
#include <cuda_runtime.h>
#include <math.h>

#define LATENT 2048
#define OBS    1024
#define CTRL   512
#define SEQ    4096
#define NCTA   128
#define RPC    16        // latent rows per CTA  (NCTA*RPC == LATENT)
#define NTHR   256
#define NREP   8         // fz replication factor

// ---------------- persistent device scratch (no allocations allowed) ----------------
__device__ __align__(16) float g_M  [(size_t)LATENT*LATENT]; // Wout^T Wout
__device__ __align__(16) float g_Gt [(size_t)SEQ*LATENT];    // (Wout^T x_t)   [t][l]
__device__ __align__(16) float g_Ut [(size_t)SEQ*LATENT];    // (Win tanh(u_t))[t][l]
__device__ __align__(16) float g_zpt[(size_t)SEQ*LATENT];    // z_projs (drive)[t][l]
__device__ __align__(16) float g_fz [2][NREP][LATENT];       // double-buffered, replicated tanh(z)
__device__ unsigned g_bar;                                   // central epoch counter

// ---------------- sync primitives (R4-proven protocol) ----------------
__device__ __forceinline__ void red_release_add(unsigned* p, unsigned v) {
  asm volatile("red.release.gpu.global.add.u32 [%0], %1;" :: "l"(p), "r"(v) : "memory");
}
__device__ __forceinline__ unsigned ld_acq(const unsigned* p) {
  unsigned v;
  asm volatile("ld.acquire.gpu.global.u32 %0, [%1];" : "=r"(v) : "l"(p) : "memory");
  return v;
}

// ---------------- generic tiled fp32 GEMM ----------------
// C[Md x Nd] row-major, C[m][n] = sum_k a(k,m)*b(k,n)
//   a(k,m) = TA ? A[m*Kd + k] : A[k*Md + m]    (optionally tanh)
//   b(k,n) = TB ? B[n*Kd + k] : B[k*Nd + n]    (optionally tanh)
// RESET: block (0,0) zeroes barrier counter and ALL fz replicas (graph-replay safety).
template<bool TA, bool TB, bool TANHA, bool TANHB, bool RESET>
__global__ void gemm_kernel(const float* __restrict__ A, const float* __restrict__ B,
                            float* __restrict__ C, int Md, int Nd, int Kd)
{
  if (RESET && blockIdx.x == 0 && blockIdx.y == 0) {
    if (threadIdx.x == 0) g_bar = 0u;
    for (int i = threadIdx.x; i < 2 * NREP * LATENT; i += blockDim.x)
      ((float*)g_fz)[i] = 0.f;
  }

  __shared__ float As[16][68];
  __shared__ float Bs[16][68];
  const int tx = threadIdx.x & 15;
  const int ty = threadIdx.x >> 4;
  const int m0 = blockIdx.y * 64;
  const int n0 = blockIdx.x * 64;
  float acc[4][4];
  #pragma unroll
  for (int i = 0; i < 4; i++)
    #pragma unroll
    for (int j = 0; j < 4; j++) acc[i][j] = 0.f;

  for (int k0 = 0; k0 < Kd; k0 += 16) {
    #pragma unroll
    for (int l = 0; l < 4; l++) {
      int i = threadIdx.x + l * 256;
      int kk, mm;
      if (TA) { kk = i & 15; mm = i >> 4; } else { kk = i >> 6; mm = i & 63; }
      float v = TA ? A[(size_t)(m0 + mm) * Kd + (k0 + kk)]
                   : A[(size_t)(k0 + kk) * Md + (m0 + mm)];
      if (TANHA) v = tanhf(v);
      As[kk][mm] = v;
      int kk2, nn;
      if (TB) { kk2 = i & 15; nn = i >> 4; } else { kk2 = i >> 6; nn = i & 63; }
      float w = TB ? B[(size_t)(n0 + nn) * Kd + (k0 + kk2)]
                   : B[(size_t)(k0 + kk2) * Nd + (n0 + nn)];
      if (TANHB) w = tanhf(w);
      Bs[kk2][nn] = w;
    }
    __syncthreads();
    #pragma unroll
    for (int kk = 0; kk < 16; kk++) {
      float a[4], bb[4];
      #pragma unroll
      for (int i = 0; i < 4; i++) a[i]  = As[kk][ty * 4 + i];
      #pragma unroll
      for (int j = 0; j < 4; j++) bb[j] = Bs[kk][tx * 4 + j];
      #pragma unroll
      for (int i = 0; i < 4; i++)
        #pragma unroll
        for (int j = 0; j < 4; j++)
          acc[i][j] += a[i] * bb[j];
    }
    __syncthreads();
  }
  #pragma unroll
  for (int i = 0; i < 4; i++)
    #pragma unroll
    for (int j = 0; j < 4; j++)
      C[(size_t)(m0 + ty * 4 + i) * Nd + (n0 + tx * 4 + j)] = acc[i][j];
}

// ---------------- persistent sequential kernel (R4 base + fz replication) ----------------
__device__ __forceinline__ void bfly4(float& a0, float& a1, float& a2, float& a3) {
  #pragma unroll
  for (int s = 16; s; s >>= 1) {
    a0 += __shfl_xor_sync(0xffffffffu, a0, s);
    a1 += __shfl_xor_sync(0xffffffffu, a1, s);
    a2 += __shfl_xor_sync(0xffffffffu, a2, s);
    a3 += __shfl_xor_sync(0xffffffffu, a3, s);
  }
}
__device__ __forceinline__ float dot4(float4 a, float4 b) {
  return a.x * b.x + a.y * b.y + a.z * b.z + a.w * b.w;
}

#define SEQ_SMEM ((32768 + 64) * 4)   // M slice + partials = 131328 bytes

__global__ void __launch_bounds__(NTHR, 1)
seq_kernel(const float* __restrict__ Wr,
           const int* __restrict__ p_it, const float* __restrict__ p_lr,
           float* __restrict__ zs_out)
{
  extern __shared__ float sm[];
  float* Ms     = sm;               // 16 x 2048 : this CTA's slice of M
  float* part_m = Ms + 32768;       // 32 : [h*16 + row] partials (M pass)
  float* part_w = part_m + 32;      // 32 : partials (Wr pass, k==0 only)

  const int b    = blockIdx.x;
  const int tid  = threadIdx.x;
  const int w    = tid >> 5, lane = tid & 31;
  const int g    = w >> 1;          // row group: rows 4g..4g+3
  const int h    = w & 1;           // K half: [1024h, 1024h+1024)
  const int rowb = b * RPC;

  // stage M slice into SMEM once
  {
    const float4* src = (const float4*)(g_M + (size_t)rowb * LATENT);
    float4* dst = (float4*)Ms;
    #pragma unroll 4
    for (int i = tid; i < RPC * LATENT / 4; i += NTHR) dst[i] = src[i];
  }

  int n_it = p_it[0];
  if (n_it <= 0 || n_it > 1000000) n_it = (int)(((const long long*)p_it)[0]);
  float lr = p_lr[0];
  if (!(lr > 1e-8f && lr < 16.f)) lr = (float)(((const double*)p_lr)[0]);

  // per-warp base pointers (float4 units; row stride = 512 float4)
  const float4* Ms4 = (const float4*)Ms + (4 * g) * 512 + h * 256;
  const float4* Wr4 = (const float4*)Wr + ((size_t)(rowb + 4 * g)) * 512 + h * 256;

  // per-row update state in registers of warp 0 lanes 0..15
  float z_own = 0.f, f_own = 0.f, drv = 0.f, g_r = 0.f, u_r = 0.f;

  unsigned ec = 0;                  // completed epochs; g_fz[ec&1] = current fz
  __syncthreads();                  // M slice staged

  for (int t = 0; t < SEQ; t++) {
    if (tid < RPC) {
      g_r = __ldg(&g_Gt[(size_t)t * LATENT + rowb + tid]);
      u_r = __ldg(&g_Ut[(size_t)t * LATENT + rowb + tid]);
    }

    for (int k = 0; k < n_it; k++) {
      // ---- fz read from this CTA's replica (L2), 8 loads in flight ----
      const float4* fz4 = (const float4*)(g_fz[ec & 1][b & (NREP - 1)]) + h * 256;
      float4 f[8];
      #pragma unroll
      for (int i = 0; i < 8; i++) f[i] = __ldcg(fz4 + i * 32 + lane);

      float a0 = 0.f, a1 = 0.f, a2 = 0.f, a3 = 0.f;
      if (k == 0) {                 // fused drive pass: Wr rows from L2/L1
        float w0 = 0.f, w1 = 0.f, w2 = 0.f, w3 = 0.f;
        #pragma unroll
        for (int i = 0; i < 8; i++) {
          const int o = i * 32 + lane;
          a0 += dot4(Ms4[o], f[i]);
          a1 += dot4(Ms4[o + 512], f[i]);
          a2 += dot4(Ms4[o + 1024], f[i]);
          a3 += dot4(Ms4[o + 1536], f[i]);
          w0 += dot4(__ldg(Wr4 + o), f[i]);
          w1 += dot4(__ldg(Wr4 + o + 512), f[i]);
          w2 += dot4(__ldg(Wr4 + o + 1024), f[i]);
          w3 += dot4(__ldg(Wr4 + o + 1536), f[i]);
        }
        bfly4(w0, w1, w2, w3);
        if (lane < 4) {
          float v = (lane == 0) ? w0 : (lane == 1) ? w1 : (lane == 2) ? w2 : w3;
          part_w[h * 16 + 4 * g + lane] = v;
        }
      } else {
        #pragma unroll
        for (int i = 0; i < 8; i++) {
          const int o = i * 32 + lane;
          a0 += dot4(Ms4[o], f[i]);
          a1 += dot4(Ms4[o + 512], f[i]);
          a2 += dot4(Ms4[o + 1024], f[i]);
          a3 += dot4(Ms4[o + 1536], f[i]);
        }
      }
      bfly4(a0, a1, a2, a3);
      if (lane < 4) {
        float v = (lane == 0) ? a0 : (lane == 1) ? a1 : (lane == 2) ? a2 : a3;
        part_m[h * 16 + 4 * g + lane] = v;
      }
      __syncthreads();                                  // partials ready

      // ---- z update: 16 register-resident rows, publish to all replicas ----
      const int wp = (int)((ec + 1) & 1);
      if (tid < RPC) {
        float s_m = part_m[tid] + part_m[16 + tid];
        if (k == 0) drv = part_w[tid] + part_w[16 + tid] + u_r;
        float dz = (z_own - drv) - (1.f - f_own * f_own) * (g_r - s_m);
        z_own -= lr * dz;
        f_own = tanhf(z_own);
        #pragma unroll
        for (int cp = 0; cp < NREP; cp++)
          g_fz[wp][cp][rowb + tid] = f_own;             // 8 x 64B coalesced publishes
        __syncwarp(0x0000ffffu);
        if (tid == 0) red_release_add(&g_bar, 1u);      // fz stores ordered before arrive
      }
      ec++;
      // ---- wait: single tight poller on the arrival line itself ----
      if (tid == 0 && !(t == SEQ - 1 && k == n_it - 1)) {
        const unsigned tgt = ec * (unsigned)NCTA;
        while (ld_acq(&g_bar) < tgt) { }
      }
      __syncthreads();
    }

    // outputs: zs[:,t] (row-major LATENT x SEQ) and z_projs (drive) as [t][l]
    if (tid < RPC) {
      zs_out[(size_t)(rowb + tid) * SEQ + t] = z_own;
      g_zpt[(size_t)t * LATENT + rowb + tid] = drv;
    }
  }
}

// ---------------- launch ----------------
extern "C" void kernel_launch(void* const* d_in, const int* in_sizes, int n_in,
                              void* d_out, int out_size)
{
  const float* inputs   = (const float*)d_in[0];  // (OBS,  SEQ)
  const float* controls = (const float*)d_in[1];  // (CTRL, SEQ)
  const float* Wr       = (const float*)d_in[2];  // (LATENT, LATENT)
  const float* Win      = (const float*)d_in[3];  // (LATENT, CTRL)
  const float* Wout     = (const float*)d_in[4];  // (OBS, LATENT)
  const int*   p_it     = (const int*)d_in[5];
  const float* p_lr     = (const float*)d_in[6];

  float* zs   = (float*)d_out;                       // (LATENT, SEQ)
  float* pred = zs + (size_t)LATENT * SEQ;           // (OBS, SEQ)

  float *pM, *pGt, *pUt, *pZpt;
  cudaGetSymbolAddress((void**)&pM,   g_M);
  cudaGetSymbolAddress((void**)&pGt,  g_Gt);
  cudaGetSymbolAddress((void**)&pUt,  g_Ut);
  cudaGetSymbolAddress((void**)&pZpt, g_zpt);

  cudaFuncSetAttribute(seq_kernel, cudaFuncAttributeMaxDynamicSharedMemorySize, SEQ_SMEM);

  dim3 thr(256);
  // M = Wout^T Wout (+ barrier/fz reset in block 0)
  gemm_kernel<false,false,false,false,true><<<dim3(LATENT/64, LATENT/64), thr>>>(Wout, Wout, pM, LATENT, LATENT, OBS);
  // Gt[t][l] = sum_i inputs[i][t] * Wout[i][l]
  gemm_kernel<false,false,false,false,false><<<dim3(LATENT/64, SEQ/64), thr>>>(inputs, Wout, pGt, SEQ, LATENT, OBS);
  // Ut[t][l] = sum_c tanh(controls[c][t]) * Win[l][c]
  gemm_kernel<false,true,true,false,false><<<dim3(LATENT/64, SEQ/64), thr>>>(controls, Win, pUt, SEQ, LATENT, CTRL);

  seq_kernel<<<NCTA, NTHR, SEQ_SMEM>>>(Wr, p_it, p_lr, zs);

  // pred[i][t] = sum_l Wout[i][l] * tanh(zpt[t][l])
  gemm_kernel<true,true,false,true,false><<<dim3(SEQ/64, OBS/64), thr>>>(Wout, pZpt, pred, OBS, SEQ, LATENT);
}

// round 10
// speedup vs baseline: 3.7745x; 1.0228x over previous
#include <cuda_runtime.h>
#include <math.h>

#define LATENT 2048
#define OBS    1024
#define CTRL   512
#define SEQ    4096
#define NCTA   128
#define RPC    16        // latent rows per CTA  (NCTA*RPC == LATENT)
#define NTHR   512       // 16 warps: 4 row-groups x 4 col-quarters
#define NREP   8         // fz replication factor

// ---------------- persistent device scratch (no allocations allowed) ----------------
__device__ __align__(16) float g_M  [(size_t)LATENT*LATENT]; // Wout^T Wout
__device__ __align__(16) float g_Gt [(size_t)SEQ*LATENT];    // (Wout^T x_t)   [t][l]
__device__ __align__(16) float g_Ut [(size_t)SEQ*LATENT];    // (Win tanh(u_t))[t][l]
__device__ __align__(16) float g_zpt[(size_t)SEQ*LATENT];    // z_projs (drive)[t][l]
__device__ __align__(16) float g_fz [2][NREP][LATENT];       // double-buffered, replicated tanh(z)
__device__ unsigned g_bar;                                   // central epoch counter

// ---------------- sync primitives ----------------
__device__ __forceinline__ unsigned atom_add_acqrel(unsigned* p, unsigned v) {
  unsigned old;
  asm volatile("atom.add.acq_rel.gpu.global.u32 %0, [%1], %2;"
               : "=r"(old) : "l"(p), "r"(v) : "memory");
  return old;
}
__device__ __forceinline__ unsigned ld_acq(const unsigned* p) {
  unsigned v;
  asm volatile("ld.acquire.gpu.global.u32 %0, [%1];" : "=r"(v) : "l"(p) : "memory");
  return v;
}

// ---------------- generic tiled fp32 GEMM ----------------
// C[Md x Nd] row-major, C[m][n] = sum_k a(k,m)*b(k,n)
//   a(k,m) = TA ? A[m*Kd + k] : A[k*Md + m]    (optionally tanh)
//   b(k,n) = TB ? B[n*Kd + k] : B[k*Nd + n]    (optionally tanh)
// RESET: block (0,0) zeroes barrier counter and ALL fz replicas (graph-replay safety).
template<bool TA, bool TB, bool TANHA, bool TANHB, bool RESET>
__global__ void gemm_kernel(const float* __restrict__ A, const float* __restrict__ B,
                            float* __restrict__ C, int Md, int Nd, int Kd)
{
  if (RESET && blockIdx.x == 0 && blockIdx.y == 0) {
    if (threadIdx.x == 0) g_bar = 0u;
    for (int i = threadIdx.x; i < 2 * NREP * LATENT; i += blockDim.x)
      ((float*)g_fz)[i] = 0.f;
  }

  __shared__ float As[16][68];
  __shared__ float Bs[16][68];
  const int tx = threadIdx.x & 15;
  const int ty = threadIdx.x >> 4;
  const int m0 = blockIdx.y * 64;
  const int n0 = blockIdx.x * 64;
  float acc[4][4];
  #pragma unroll
  for (int i = 0; i < 4; i++)
    #pragma unroll
    for (int j = 0; j < 4; j++) acc[i][j] = 0.f;

  for (int k0 = 0; k0 < Kd; k0 += 16) {
    #pragma unroll
    for (int l = 0; l < 4; l++) {
      int i = threadIdx.x + l * 256;
      int kk, mm;
      if (TA) { kk = i & 15; mm = i >> 4; } else { kk = i >> 6; mm = i & 63; }
      float v = TA ? A[(size_t)(m0 + mm) * Kd + (k0 + kk)]
                   : A[(size_t)(k0 + kk) * Md + (m0 + mm)];
      if (TANHA) v = tanhf(v);
      As[kk][mm] = v;
      int kk2, nn;
      if (TB) { kk2 = i & 15; nn = i >> 4; } else { kk2 = i >> 6; nn = i & 63; }
      float w = TB ? B[(size_t)(n0 + nn) * Kd + (k0 + kk2)]
                   : B[(size_t)(k0 + kk2) * Nd + (n0 + nn)];
      if (TANHB) w = tanhf(w);
      Bs[kk2][nn] = w;
    }
    __syncthreads();
    #pragma unroll
    for (int kk = 0; kk < 16; kk++) {
      float a[4], bb[4];
      #pragma unroll
      for (int i = 0; i < 4; i++) a[i]  = As[kk][ty * 4 + i];
      #pragma unroll
      for (int j = 0; j < 4; j++) bb[j] = Bs[kk][tx * 4 + j];
      #pragma unroll
      for (int i = 0; i < 4; i++)
        #pragma unroll
        for (int j = 0; j < 4; j++)
          acc[i][j] += a[i] * bb[j];
    }
    __syncthreads();
  }
  #pragma unroll
  for (int i = 0; i < 4; i++)
    #pragma unroll
    for (int j = 0; j < 4; j++)
      C[(size_t)(m0 + ty * 4 + i) * Nd + (n0 + tx * 4 + j)] = acc[i][j];
}

// ---------------- persistent sequential kernel ----------------
__device__ __forceinline__ void bfly4(float& a0, float& a1, float& a2, float& a3) {
  #pragma unroll
  for (int s = 16; s; s >>= 1) {
    a0 += __shfl_xor_sync(0xffffffffu, a0, s);
    a1 += __shfl_xor_sync(0xffffffffu, a1, s);
    a2 += __shfl_xor_sync(0xffffffffu, a2, s);
    a3 += __shfl_xor_sync(0xffffffffu, a3, s);
  }
}
__device__ __forceinline__ float dot4(float4 a, float4 b) {
  return a.x * b.x + a.y * b.y + a.z * b.z + a.w * b.w;
}

#define SEQ_SMEM ((32768 + 128) * 4)   // M slice + partials(64+64) = 131584 bytes

__global__ void __launch_bounds__(NTHR, 1)
seq_kernel(const float* __restrict__ Wr,
           const int* __restrict__ p_it, const float* __restrict__ p_lr,
           float* __restrict__ zs_out)
{
  extern __shared__ float sm[];
  float* Ms     = sm;               // 16 x 2048 : this CTA's slice of M
  float* part_m = Ms + 32768;       // 64 : [(row)*4 + quarter] partials (M pass)
  float* part_w = part_m + 64;      // 64 : partials (Wr pass, k==0 only)

  const int b    = blockIdx.x;
  const int tid  = threadIdx.x;
  const int w    = tid >> 5, lane = tid & 31;
  const int g    = w >> 2;          // row group: rows 4g..4g+3
  const int q    = w & 3;           // K quarter: cols [512q, 512q+512)
  const int rowb = b * RPC;

  // stage M slice into SMEM once
  {
    const float4* src = (const float4*)(g_M + (size_t)rowb * LATENT);
    float4* dst = (float4*)Ms;
    #pragma unroll 4
    for (int i = tid; i < RPC * LATENT / 4; i += NTHR) dst[i] = src[i];
  }

  int n_it = p_it[0];
  if (n_it <= 0 || n_it > 1000000) n_it = (int)(((const long long*)p_it)[0]);
  float lr = p_lr[0];
  if (!(lr > 1e-8f && lr < 16.f)) lr = (float)(((const double*)p_lr)[0]);

  // per-warp base pointers (float4 units; row stride = 512 float4)
  const float4* Ms4 = (const float4*)Ms + (4 * g) * 512 + q * 128;
  const float4* Wr4 = (const float4*)Wr + ((size_t)(rowb + 4 * g)) * 512 + q * 128;

  // per-row update state in registers of warp 0 lanes 0..15
  float z_own = 0.f, f_own = 0.f, drv = 0.f, g_r = 0.f, u_r = 0.f;

  unsigned ec = 0;                  // completed epochs; g_fz[ec&1] = current fz
  __syncthreads();                  // M slice staged

  for (int t = 0; t < SEQ; t++) {
    if (tid < RPC) {
      g_r = __ldg(&g_Gt[(size_t)t * LATENT + rowb + tid]);
      u_r = __ldg(&g_Ut[(size_t)t * LATENT + rowb + tid]);
    }

    for (int k = 0; k < n_it; k++) {
      // ---- fz quarter from this CTA's replica (L2), 4 loads in flight ----
      const float4* fz4 = (const float4*)(g_fz[ec & 1][b & (NREP - 1)]) + q * 128;
      float4 f[4];
      #pragma unroll
      for (int i = 0; i < 4; i++) f[i] = __ldcg(fz4 + i * 32 + lane);

      float a0 = 0.f, a1 = 0.f, a2 = 0.f, a3 = 0.f;
      #pragma unroll
      for (int i = 0; i < 4; i++) {
        const int o = i * 32 + lane;
        a0 += dot4(Ms4[o], f[i]);
        a1 += dot4(Ms4[o + 512], f[i]);
        a2 += dot4(Ms4[o + 1024], f[i]);
        a3 += dot4(Ms4[o + 1536], f[i]);
      }
      if (k == 0) {                 // fused drive pass: Wr rows from L2
        float w0 = 0.f, w1 = 0.f, w2 = 0.f, w3 = 0.f;
        #pragma unroll
        for (int i = 0; i < 4; i++) {
          const int o = i * 32 + lane;
          w0 += dot4(__ldg(Wr4 + o), f[i]);
          w1 += dot4(__ldg(Wr4 + o + 512), f[i]);
          w2 += dot4(__ldg(Wr4 + o + 1024), f[i]);
          w3 += dot4(__ldg(Wr4 + o + 1536), f[i]);
        }
        bfly4(w0, w1, w2, w3);
        if (lane < 4) {
          float v = (lane == 0) ? w0 : (lane == 1) ? w1 : (lane == 2) ? w2 : w3;
          part_w[(4 * g + lane) * 4 + q] = v;
        }
      }
      bfly4(a0, a1, a2, a3);
      if (lane < 4) {
        float v = (lane == 0) ? a0 : (lane == 1) ? a1 : (lane == 2) ? a2 : a3;
        part_m[(4 * g + lane) * 4 + q] = v;
      }
      __syncthreads();                                  // partials ready

      // ---- z update: 16 register-resident rows, publish, arrive ----
      const unsigned en = ec + 1;
      bool last_arriver = false;
      if (tid < RPC) {
        float4 pm = *(const float4*)&part_m[tid * 4];
        float s_m = (pm.x + pm.y) + (pm.z + pm.w);
        if (k == 0) {
          float4 pw = *(const float4*)&part_w[tid * 4];
          drv = (pw.x + pw.y) + (pw.z + pw.w) + u_r;
        }
        float dz = (z_own - drv) - (1.f - f_own * f_own) * (g_r - s_m);
        z_own -= lr * dz;
        f_own = tanhf(z_own);
        #pragma unroll
        for (int cp = 0; cp < NREP; cp++)
          g_fz[en & 1][cp][rowb + tid] = f_own;         // 8 x 64B coalesced publishes
        __syncwarp(0x0000ffffu);
        if (tid == 0) {
          unsigned old = atom_add_acqrel(&g_bar, 1u);   // fz stores ordered before arrive
          last_arriver = (old == en * (unsigned)NCTA - 1u);
        }
      }
      ec = en;
      // ---- wait: single tight poller (skipped by the epoch-completing CTA) ----
      if (tid == 0 && !last_arriver && !(t == SEQ - 1 && k == n_it - 1)) {
        const unsigned tgt = ec * (unsigned)NCTA;
        while (ld_acq(&g_bar) < tgt) { }
      }
      __syncthreads();
    }

    // outputs: zs[:,t] (row-major LATENT x SEQ) and z_projs (drive) as [t][l]
    if (tid < RPC) {
      zs_out[(size_t)(rowb + tid) * SEQ + t] = z_own;
      g_zpt[(size_t)t * LATENT + rowb + tid] = drv;
    }
  }
}

// ---------------- launch ----------------
extern "C" void kernel_launch(void* const* d_in, const int* in_sizes, int n_in,
                              void* d_out, int out_size)
{
  const float* inputs   = (const float*)d_in[0];  // (OBS,  SEQ)
  const float* controls = (const float*)d_in[1];  // (CTRL, SEQ)
  const float* Wr       = (const float*)d_in[2];  // (LATENT, LATENT)
  const float* Win      = (const float*)d_in[3];  // (LATENT, CTRL)
  const float* Wout     = (const float*)d_in[4];  // (OBS, LATENT)
  const int*   p_it     = (const int*)d_in[5];
  const float* p_lr     = (const float*)d_in[6];

  float* zs   = (float*)d_out;                       // (LATENT, SEQ)
  float* pred = zs + (size_t)LATENT * SEQ;           // (OBS, SEQ)

  float *pM, *pGt, *pUt, *pZpt;
  cudaGetSymbolAddress((void**)&pM,   g_M);
  cudaGetSymbolAddress((void**)&pGt,  g_Gt);
  cudaGetSymbolAddress((void**)&pUt,  g_Ut);
  cudaGetSymbolAddress((void**)&pZpt, g_zpt);

  cudaFuncSetAttribute(seq_kernel, cudaFuncAttributeMaxDynamicSharedMemorySize, SEQ_SMEM);

  dim3 thr(256);
  // M = Wout^T Wout (+ barrier/fz reset in block 0)
  gemm_kernel<false,false,false,false,true><<<dim3(LATENT/64, LATENT/64), thr>>>(Wout, Wout, pM, LATENT, LATENT, OBS);
  // Gt[t][l] = sum_i inputs[i][t] * Wout[i][l]
  gemm_kernel<false,false,false,false,false><<<dim3(LATENT/64, SEQ/64), thr>>>(inputs, Wout, pGt, SEQ, LATENT, OBS);
  // Ut[t][l] = sum_c tanh(controls[c][t]) * Win[l][c]
  gemm_kernel<false,true,true,false,false><<<dim3(LATENT/64, SEQ/64), thr>>>(controls, Win, pUt, SEQ, LATENT, CTRL);

  seq_kernel<<<NCTA, NTHR, SEQ_SMEM>>>(Wr, p_it, p_lr, zs);

  // pred[i][t] = sum_l Wout[i][l] * tanh(zpt[t][l])
  gemm_kernel<true,true,false,true,false><<<dim3(SEQ/64, OBS/64), thr>>>(Wout, pZpt, pred, OBS, SEQ, LATENT);
}

// round 11
// speedup vs baseline: 3.7753x; 1.0002x over previous
#include <cuda_runtime.h>
#include <math.h>

#define LATENT 2048
#define OBS    1024
#define CTRL   512
#define SEQ    4096
#define NCTA   128
#define RPC    16        // latent rows per CTA  (NCTA*RPC == LATENT)
#define NTHR   512       // 16 warps: 4 row-groups x 4 col-quarters
#define NREP   8         // fz replication factor

// ---------------- persistent device scratch (no allocations allowed) ----------------
__device__ __align__(16) float g_M  [(size_t)LATENT*LATENT]; // Wout^T Wout
__device__ __align__(16) float g_Gt [(size_t)SEQ*LATENT];    // (Wout^T x_t)   [t][l]
__device__ __align__(16) float g_Ut [(size_t)SEQ*LATENT];    // (Win tanh(u_t))[t][l]
__device__ __align__(16) float g_zpt[(size_t)SEQ*LATENT];    // z_projs (drive)[t][l]
__device__ __align__(16) float g_fz [2][NREP][LATENT];       // double-buffered, replicated tanh(z)
__device__ unsigned g_bar;                                   // central epoch counter

// ---------------- sync primitives ----------------
__device__ __forceinline__ unsigned atom_add_acqrel(unsigned* p, unsigned v) {
  unsigned old;
  asm volatile("atom.add.acq_rel.gpu.global.u32 %0, [%1], %2;"
               : "=r"(old) : "l"(p), "r"(v) : "memory");
  return old;
}
__device__ __forceinline__ unsigned ld_acq(const unsigned* p) {
  unsigned v;
  asm volatile("ld.acquire.gpu.global.u32 %0, [%1];" : "=r"(v) : "l"(p) : "memory");
  return v;
}

// ---------------- 128x128-tile / 8x8-microtile fp32 GEMM ----------------
// C[Md x Nd] row-major, C[m][n] = sum_k a(k,m)*b(k,n)
//   a(k,m) = TA ? A[m*Kd + k] : A[k*Md + m]    (optionally tanh)
//   b(k,n) = TB ? B[n*Kd + k] : B[k*Nd + n]    (optionally tanh)
// All Md/Nd multiples of 128, Kd multiples of 16 for this problem.
// RESET: block (0,0) zeroes barrier counter and ALL fz replicas (graph-replay safety).
template<bool TA, bool TB, bool TANHA, bool TANHB, bool RESET>
__global__ void __launch_bounds__(256)
gemm_kernel(const float* __restrict__ A, const float* __restrict__ B,
            float* __restrict__ C, int Md, int Nd, int Kd)
{
  if (RESET && blockIdx.x == 0 && blockIdx.y == 0) {
    if (threadIdx.x == 0) g_bar = 0u;
    for (int i = threadIdx.x; i < 2 * NREP * LATENT; i += blockDim.x)
      ((float*)g_fz)[i] = 0.f;
  }

  __shared__ __align__(16) float As[16][132];   // 132 = 128 + 4 pad (16B-aligned rows)
  __shared__ __align__(16) float Bs[16][132];
  const int tid = threadIdx.x;
  const int tx  = tid & 15;          // 16 col-threads
  const int ty  = tid >> 4;          // 16 row-threads
  const int m0  = blockIdx.y * 128;
  const int n0  = blockIdx.x * 128;

  float acc[8][8];
  #pragma unroll
  for (int i = 0; i < 8; i++)
    #pragma unroll
    for (int j = 0; j < 8; j++) acc[i][j] = 0.f;

  for (int k0 = 0; k0 < Kd; k0 += 16) {
    // ---- stage tiles: 2048 elements each, 8 per thread, TA/TB-aware coalescing ----
    #pragma unroll
    for (int l = 0; l < 8; l++) {
      const int i = tid + l * 256;
      int kk, mm;
      if (TA) { kk = i & 15; mm = i >> 4; }       // coalesced along K
      else    { kk = i >> 7; mm = i & 127; }      // coalesced along M
      float v = TA ? A[(size_t)(m0 + mm) * Kd + (k0 + kk)]
                   : A[(size_t)(k0 + kk) * Md + (m0 + mm)];
      if (TANHA) v = tanhf(v);
      As[kk][mm] = v;
      int kk2, nn;
      if (TB) { kk2 = i & 15; nn = i >> 4; }
      else    { kk2 = i >> 7; nn = i & 127; }
      float w = TB ? B[(size_t)(n0 + nn) * Kd + (k0 + kk2)]
                   : B[(size_t)(k0 + kk2) * Nd + (n0 + nn)];
      if (TANHB) w = tanhf(w);
      Bs[kk2][nn] = w;
    }
    __syncthreads();
    // ---- 8x8 microtile FMA over the 16-deep panel ----
    #pragma unroll
    for (int kk = 0; kk < 16; kk++) {
      float4 a0 = *(const float4*)&As[kk][ty * 8];
      float4 a1 = *(const float4*)&As[kk][ty * 8 + 4];
      float4 b0 = *(const float4*)&Bs[kk][tx * 8];
      float4 b1 = *(const float4*)&Bs[kk][tx * 8 + 4];
      const float a[8] = {a0.x, a0.y, a0.z, a0.w, a1.x, a1.y, a1.z, a1.w};
      const float b[8] = {b0.x, b0.y, b0.z, b0.w, b1.x, b1.y, b1.z, b1.w};
      #pragma unroll
      for (int i = 0; i < 8; i++)
        #pragma unroll
        for (int j = 0; j < 8; j++)
          acc[i][j] += a[i] * b[j];
    }
    __syncthreads();
  }
  // ---- coalesced float4 stores ----
  #pragma unroll
  for (int i = 0; i < 8; i++) {
    float* crow = C + (size_t)(m0 + ty * 8 + i) * Nd + n0 + tx * 8;
    *(float4*)crow       = make_float4(acc[i][0], acc[i][1], acc[i][2], acc[i][3]);
    *(float4*)(crow + 4) = make_float4(acc[i][4], acc[i][5], acc[i][6], acc[i][7]);
  }
}

// ---------------- persistent sequential kernel ----------------
__device__ __forceinline__ void bfly4(float& a0, float& a1, float& a2, float& a3) {
  #pragma unroll
  for (int s = 16; s; s >>= 1) {
    a0 += __shfl_xor_sync(0xffffffffu, a0, s);
    a1 += __shfl_xor_sync(0xffffffffu, a1, s);
    a2 += __shfl_xor_sync(0xffffffffu, a2, s);
    a3 += __shfl_xor_sync(0xffffffffu, a3, s);
  }
}
__device__ __forceinline__ float dot4(float4 a, float4 b) {
  return a.x * b.x + a.y * b.y + a.z * b.z + a.w * b.w;
}

#define SEQ_SMEM ((32768 + 128) * 4)   // M slice + partials(64+64) = 131584 bytes

__global__ void __launch_bounds__(NTHR, 1)
seq_kernel(const float* __restrict__ Wr,
           const int* __restrict__ p_it, const float* __restrict__ p_lr,
           float* __restrict__ zs_out)
{
  extern __shared__ float sm[];
  float* Ms     = sm;               // 16 x 2048 : this CTA's slice of M
  float* part_m = Ms + 32768;       // 64 : [(row)*4 + quarter] partials (M pass)
  float* part_w = part_m + 64;      // 64 : partials (Wr pass, k==0 only)

  const int b    = blockIdx.x;
  const int tid  = threadIdx.x;
  const int w    = tid >> 5, lane = tid & 31;
  const int g    = w >> 2;          // row group: rows 4g..4g+3
  const int q    = w & 3;           // K quarter: cols [512q, 512q+512)
  const int rowb = b * RPC;

  // stage M slice into SMEM once
  {
    const float4* src = (const float4*)(g_M + (size_t)rowb * LATENT);
    float4* dst = (float4*)Ms;
    #pragma unroll 4
    for (int i = tid; i < RPC * LATENT / 4; i += NTHR) dst[i] = src[i];
  }

  int n_it = p_it[0];
  if (n_it <= 0 || n_it > 1000000) n_it = (int)(((const long long*)p_it)[0]);
  float lr = p_lr[0];
  if (!(lr > 1e-8f && lr < 16.f)) lr = (float)(((const double*)p_lr)[0]);

  // per-warp base pointers (float4 units; row stride = 512 float4)
  const float4* Ms4 = (const float4*)Ms + (4 * g) * 512 + q * 128;
  const float4* Wr4 = (const float4*)Wr + ((size_t)(rowb + 4 * g)) * 512 + q * 128;

  // per-row update state in registers of warp 0 lanes 0..15
  float z_own = 0.f, f_own = 0.f, drv = 0.f, g_r = 0.f, u_r = 0.f;

  unsigned ec = 0;                  // completed epochs; g_fz[ec&1] = current fz
  __syncthreads();                  // M slice staged

  for (int t = 0; t < SEQ; t++) {
    if (tid < RPC) {
      g_r = __ldg(&g_Gt[(size_t)t * LATENT + rowb + tid]);
      u_r = __ldg(&g_Ut[(size_t)t * LATENT + rowb + tid]);
    }

    for (int k = 0; k < n_it; k++) {
      // ---- fz quarter from this CTA's replica (L2), 4 loads in flight ----
      const float4* fz4 = (const float4*)(g_fz[ec & 1][b & (NREP - 1)]) + q * 128;
      float4 f[4];
      #pragma unroll
      for (int i = 0; i < 4; i++) f[i] = __ldcg(fz4 + i * 32 + lane);

      float a0 = 0.f, a1 = 0.f, a2 = 0.f, a3 = 0.f;
      #pragma unroll
      for (int i = 0; i < 4; i++) {
        const int o = i * 32 + lane;
        a0 += dot4(Ms4[o], f[i]);
        a1 += dot4(Ms4[o + 512], f[i]);
        a2 += dot4(Ms4[o + 1024], f[i]);
        a3 += dot4(Ms4[o + 1536], f[i]);
      }
      if (k == 0) {                 // fused drive pass: Wr rows from L2
        float w0 = 0.f, w1 = 0.f, w2 = 0.f, w3 = 0.f;
        #pragma unroll
        for (int i = 0; i < 4; i++) {
          const int o = i * 32 + lane;
          w0 += dot4(__ldg(Wr4 + o), f[i]);
          w1 += dot4(__ldg(Wr4 + o + 512), f[i]);
          w2 += dot4(__ldg(Wr4 + o + 1024), f[i]);
          w3 += dot4(__ldg(Wr4 + o + 1536), f[i]);
        }
        bfly4(w0, w1, w2, w3);
        if (lane < 4) {
          float v = (lane == 0) ? w0 : (lane == 1) ? w1 : (lane == 2) ? w2 : w3;
          part_w[(4 * g + lane) * 4 + q] = v;
        }
      }
      bfly4(a0, a1, a2, a3);
      if (lane < 4) {
        float v = (lane == 0) ? a0 : (lane == 1) ? a1 : (lane == 2) ? a2 : a3;
        part_m[(4 * g + lane) * 4 + q] = v;
      }
      __syncthreads();                                  // partials ready

      // ---- z update: 16 register-resident rows, publish, arrive ----
      const unsigned en = ec + 1;
      bool last_arriver = false;
      if (tid < RPC) {
        float4 pm = *(const float4*)&part_m[tid * 4];
        float s_m = (pm.x + pm.y) + (pm.z + pm.w);
        if (k == 0) {
          float4 pw = *(const float4*)&part_w[tid * 4];
          drv = (pw.x + pw.y) + (pw.z + pw.w) + u_r;
        }
        float dz = (z_own - drv) - (1.f - f_own * f_own) * (g_r - s_m);
        z_own -= lr * dz;
        f_own = tanhf(z_own);
        #pragma unroll
        for (int cp = 0; cp < NREP; cp++)
          g_fz[en & 1][cp][rowb + tid] = f_own;         // 8 x 64B coalesced publishes
        __syncwarp(0x0000ffffu);
        if (tid == 0) {
          unsigned old = atom_add_acqrel(&g_bar, 1u);   // fz stores ordered before arrive
          last_arriver = (old == en * (unsigned)NCTA - 1u);
        }
        if (k == n_it - 1) {
          // per-step outputs issued AFTER the arrive, overlapping the poll below
          zs_out[(size_t)(rowb + tid) * SEQ + t] = z_own;
          g_zpt[(size_t)t * LATENT + rowb + tid] = drv;
        }
      }
      ec = en;
      // ---- wait: single tight poller (skipped by the epoch-completing CTA) ----
      if (tid == 0 && !last_arriver && !(t == SEQ - 1 && k == n_it - 1)) {
        const unsigned tgt = ec * (unsigned)NCTA;
        while (ld_acq(&g_bar) < tgt) { }
      }
      __syncthreads();
    }
  }
}

// ---------------- launch ----------------
extern "C" void kernel_launch(void* const* d_in, const int* in_sizes, int n_in,
                              void* d_out, int out_size)
{
  const float* inputs   = (const float*)d_in[0];  // (OBS,  SEQ)
  const float* controls = (const float*)d_in[1];  // (CTRL, SEQ)
  const float* Wr       = (const float*)d_in[2];  // (LATENT, LATENT)
  const float* Win      = (const float*)d_in[3];  // (LATENT, CTRL)
  const float* Wout     = (const float*)d_in[4];  // (OBS, LATENT)
  const int*   p_it     = (const int*)d_in[5];
  const float* p_lr     = (const float*)d_in[6];

  float* zs   = (float*)d_out;                       // (LATENT, SEQ)
  float* pred = zs + (size_t)LATENT * SEQ;           // (OBS, SEQ)

  float *pM, *pGt, *pUt, *pZpt;
  cudaGetSymbolAddress((void**)&pM,   g_M);
  cudaGetSymbolAddress((void**)&pGt,  g_Gt);
  cudaGetSymbolAddress((void**)&pUt,  g_Ut);
  cudaGetSymbolAddress((void**)&pZpt, g_zpt);

  cudaFuncSetAttribute(seq_kernel, cudaFuncAttributeMaxDynamicSharedMemorySize, SEQ_SMEM);

  dim3 thr(256);
  // M = Wout^T Wout (+ barrier/fz reset in block 0)
  gemm_kernel<false,false,false,false,true><<<dim3(LATENT/128, LATENT/128), thr>>>(Wout, Wout, pM, LATENT, LATENT, OBS);
  // Gt[t][l] = sum_i inputs[i][t] * Wout[i][l]
  gemm_kernel<false,false,false,false,false><<<dim3(LATENT/128, SEQ/128), thr>>>(inputs, Wout, pGt, SEQ, LATENT, OBS);
  // Ut[t][l] = sum_c tanh(controls[c][t]) * Win[l][c]
  gemm_kernel<false,true,true,false,false><<<dim3(LATENT/128, SEQ/128), thr>>>(controls, Win, pUt, SEQ, LATENT, CTRL);

  seq_kernel<<<NCTA, NTHR, SEQ_SMEM>>>(Wr, p_it, p_lr, zs);

  // pred[i][t] = sum_l Wout[i][l] * tanh(zpt[t][l])
  gemm_kernel<true,true,false,true,false><<<dim3(SEQ/128, OBS/128), thr>>>(Wout, pZpt, pred, OBS, SEQ, LATENT);
}